// round 2
// baseline (speedup 1.0000x reference)
#include <cuda_runtime.h>
#include <cuda_bf16.h>
#include <math.h>

// Problem constants
#define BATCH 2
#define SEQ   2048
#define DMODEL 1024
#define NHEAD 16
#define HDIM  64
#define MTOK  (BATCH*SEQ)        // 4096 tokens

// ---------------------------------------------------------------------------
// Scratch (device globals; allocation-free)
// ---------------------------------------------------------------------------
__device__ float g_q[MTOK * DMODEL];
__device__ float g_k[MTOK * DMODEL];
__device__ float g_v[MTOK * DMODEL];
__device__ float g_attn[MTOK * DMODEL];

// ---------------------------------------------------------------------------
// SGEMM: C[M,N] = A[M,K] @ W[K,N] + bias  (128x128x8 tile, 256 thr, 8x8 micro)
// M,N,K all multiples of 128/128/8 here (4096,1024,1024).
// ---------------------------------------------------------------------------
#define BM 128
#define BN 128
#define BKK 8
__global__ __launch_bounds__(256) void sgemm_bias(
    const float* __restrict__ A, const float* __restrict__ W,
    const float* __restrict__ bias, float* __restrict__ C,
    int M, int N, int K)
{
    __shared__ float As[BKK][BM];
    __shared__ float Bs[BKK][BN];

    const int tid = threadIdx.x;
    const int bm = blockIdx.y * BM;
    const int bn = blockIdx.x * BN;

    const int arow = tid >> 1;            // 0..127
    const int acol = (tid & 1) * 4;       // 0 or 4
    const int brow = tid >> 5;            // 0..7
    const int bcol = (tid & 31) * 4;      // 0..124

    const int ty = tid >> 4;              // 0..15
    const int tx = tid & 15;              // 0..15

    float acc[8][8];
#pragma unroll
    for (int i = 0; i < 8; i++)
#pragma unroll
        for (int j = 0; j < 8; j++) acc[i][j] = 0.f;

    const float* Aptr = A + (size_t)(bm + arow) * K + acol;
    const float* Wptr = W + (size_t)brow * N + bn + bcol;

    for (int k0 = 0; k0 < K; k0 += BKK) {
        float4 a4 = *(const float4*)(Aptr + k0);
        As[acol + 0][arow] = a4.x;
        As[acol + 1][arow] = a4.y;
        As[acol + 2][arow] = a4.z;
        As[acol + 3][arow] = a4.w;
        float4 b4 = *(const float4*)(Wptr + (size_t)k0 * N);
        *(float4*)&Bs[brow][bcol] = b4;
        __syncthreads();

#pragma unroll
        for (int k = 0; k < BKK; k++) {
            float ra[8], rb[8];
#pragma unroll
            for (int i = 0; i < 8; i++) ra[i] = As[k][ty * 8 + i];
#pragma unroll
            for (int j = 0; j < 8; j++) rb[j] = Bs[k][tx * 8 + j];
#pragma unroll
            for (int i = 0; i < 8; i++)
#pragma unroll
                for (int j = 0; j < 8; j++)
                    acc[i][j] = fmaf(ra[i], rb[j], acc[i][j]);
        }
        __syncthreads();
    }

    // epilogue: add bias, store
    float bb[8];
#pragma unroll
    for (int j = 0; j < 8; j++) bb[j] = bias[bn + tx * 8 + j];

#pragma unroll
    for (int i = 0; i < 8; i++) {
        const int row = bm + ty * 8 + i;
        float* Crow = C + (size_t)row * N + bn + tx * 8;
        float4 c0, c1;
        c0.x = acc[i][0] + bb[0]; c0.y = acc[i][1] + bb[1];
        c0.z = acc[i][2] + bb[2]; c0.w = acc[i][3] + bb[3];
        c1.x = acc[i][4] + bb[4]; c1.y = acc[i][5] + bb[5];
        c1.z = acc[i][6] + bb[6]; c1.w = acc[i][7] + bb[7];
        *(float4*)(Crow + 0) = c0;
        *(float4*)(Crow + 4) = c1;
    }
}

// ---------------------------------------------------------------------------
// Flash attention: one block per (b, h, 64-query tile).
// 256 threads = 64 rows x 4 lanes; each thread owns 16 key-cols (scores) and
// 16 V-dims (accumulation) for its row. Online softmax, causal + padding mask.
// Smem: Qs, Ks, Vs, Ps each [64][68] fp32 (stride 68 avoids bank conflicts).
// ---------------------------------------------------------------------------
#define TS 64
#define TSTR 68
#define ATTN_SMEM (4 * TS * TSTR * (int)sizeof(float))

__global__ __launch_bounds__(256) void attn_kernel(
    const float* __restrict__ Q, const float* __restrict__ K,
    const float* __restrict__ V, const unsigned char* __restrict__ maskp,
    float* __restrict__ O)
{
    extern __shared__ float sm[];
    float* Qs = sm;
    float* Ks = Qs + TS * TSTR;
    float* Vs = Ks + TS * TSTR;
    float* Ps = Vs + TS * TSTR;

    const int tid = threadIdx.x;
    const int qt = blockIdx.x;     // query tile 0..31
    const int h  = blockIdx.y;     // head
    const int b  = blockIdx.z;     // batch

    const int r  = tid >> 2;       // row within tile 0..63
    const int qd = tid & 3;        // quarter lane 0..3
    const int j0 = qd * 16;        // key slice / dim slice base

    const int tok0 = b * SEQ + qt * TS;

    // load Q tile, pre-scaled by 1/sqrt(64)
    {
        const float* Qg = Q + (size_t)tok0 * DMODEL + h * HDIM;
#pragma unroll
        for (int i = 0; i < 4; i++) {
            int f4 = tid + i * 256;          // 0..1023
            int rr = f4 >> 4;                // row 0..63
            int c4 = f4 & 15;                // float4 col 0..15
            float4 v = *(const float4*)(Qg + (size_t)rr * DMODEL + c4 * 4);
            v.x *= 0.125f; v.y *= 0.125f; v.z *= 0.125f; v.w *= 0.125f;
            *(float4*)&Qs[rr * TSTR + c4 * 4] = v;
        }
    }

    float m = -1e30f, l = 0.f;
    float acc[16];
#pragma unroll
    for (int i = 0; i < 16; i++) acc[i] = 0.f;

    const int qglob = qt * TS + r;

    for (int kt = 0; kt <= qt; kt++) {
        __syncthreads();   // prior accumulation done (and Q ready on first iter)

        // load K, V tiles
        {
            const float* Kg = K + (size_t)(b * SEQ + kt * TS) * DMODEL + h * HDIM;
            const float* Vg = V + (size_t)(b * SEQ + kt * TS) * DMODEL + h * HDIM;
#pragma unroll
            for (int i = 0; i < 4; i++) {
                int f4 = tid + i * 256;
                int rr = f4 >> 4;
                int c4 = f4 & 15;
                *(float4*)&Ks[rr * TSTR + c4 * 4] =
                    *(const float4*)(Kg + (size_t)rr * DMODEL + c4 * 4);
                *(float4*)&Vs[rr * TSTR + c4 * 4] =
                    *(const float4*)(Vg + (size_t)rr * DMODEL + c4 * 4);
            }
        }
        __syncthreads();

        // scores for this lane's 16 keys
        float s[16];
#pragma unroll
        for (int jj = 0; jj < 16; jj++) s[jj] = 0.f;
#pragma unroll
        for (int d4 = 0; d4 < 16; d4++) {
            float4 q4 = *(const float4*)&Qs[r * TSTR + d4 * 4];
#pragma unroll
            for (int jj = 0; jj < 16; jj++) {
                float4 k4 = *(const float4*)&Ks[(j0 + jj) * TSTR + d4 * 4];
                s[jj] = fmaf(q4.x, k4.x, s[jj]);
                s[jj] = fmaf(q4.y, k4.y, s[jj]);
                s[jj] = fmaf(q4.z, k4.z, s[jj]);
                s[jj] = fmaf(q4.w, k4.w, s[jj]);
            }
        }

        // masks (causal + padding)
        const int kbase = kt * TS + j0;
#pragma unroll
        for (int jj = 0; jj < 16; jj++) {
            int kglob = kbase + jj;
            if (kglob > qglob || maskp[b * SEQ + kglob]) s[jj] = -1e30f;
        }

        // row max across 16 local + 4 lanes
        float tm = s[0];
#pragma unroll
        for (int jj = 1; jj < 16; jj++) tm = fmaxf(tm, s[jj]);
        tm = fmaxf(tm, __shfl_xor_sync(0xffffffffu, tm, 1));
        tm = fmaxf(tm, __shfl_xor_sync(0xffffffffu, tm, 2));
        float newm = fmaxf(m, tm);

        float ls = 0.f;
#pragma unroll
        for (int jj = 0; jj < 16; jj++) {
            float p = (s[jj] > -1e29f) ? __expf(s[jj] - newm) : 0.f;
            ls += p;
            Ps[r * TSTR + j0 + jj] = p;
        }
        ls += __shfl_xor_sync(0xffffffffu, ls, 1);
        ls += __shfl_xor_sync(0xffffffffu, ls, 2);

        float corr = (m > -1e29f) ? __expf(m - newm) : 0.f;
        l = l * corr + ls;
#pragma unroll
        for (int dd = 0; dd < 16; dd++) acc[dd] *= corr;
        m = newm;

        __syncthreads();   // Ps visible to all lanes of the row

        // accumulate O += P @ V on this lane's 16-dim slice
#pragma unroll 4
        for (int j = 0; j < TS; j++) {
            float pv = Ps[r * TSTR + j];
            const float4* vr = (const float4*)&Vs[j * TSTR + j0];
            float4 v0 = vr[0], v1 = vr[1], v2 = vr[2], v3 = vr[3];
            acc[0]  = fmaf(pv, v0.x, acc[0]);  acc[1]  = fmaf(pv, v0.y, acc[1]);
            acc[2]  = fmaf(pv, v0.z, acc[2]);  acc[3]  = fmaf(pv, v0.w, acc[3]);
            acc[4]  = fmaf(pv, v1.x, acc[4]);  acc[5]  = fmaf(pv, v1.y, acc[5]);
            acc[6]  = fmaf(pv, v1.z, acc[6]);  acc[7]  = fmaf(pv, v1.w, acc[7]);
            acc[8]  = fmaf(pv, v2.x, acc[8]);  acc[9]  = fmaf(pv, v2.y, acc[9]);
            acc[10] = fmaf(pv, v2.z, acc[10]); acc[11] = fmaf(pv, v2.w, acc[11]);
            acc[12] = fmaf(pv, v3.x, acc[12]); acc[13] = fmaf(pv, v3.y, acc[13]);
            acc[14] = fmaf(pv, v3.z, acc[14]); acc[15] = fmaf(pv, v3.w, acc[15]);
        }
    }

    const float rl = (l > 0.f) ? (1.f / l) : 0.f;
    float* Og = O + (size_t)(tok0 + r) * DMODEL + h * HDIM + j0;
#pragma unroll
    for (int t = 0; t < 4; t++) {
        float4 o;
        o.x = acc[t * 4 + 0] * rl;
        o.y = acc[t * 4 + 1] * rl;
        o.z = acc[t * 4 + 2] * rl;
        o.w = acc[t * 4 + 3] * rl;
        *(float4*)(Og + t * 4) = o;
    }
}

// ---------------------------------------------------------------------------
// Launch
// ---------------------------------------------------------------------------
extern "C" void kernel_launch(void* const* d_in, const int* in_sizes, int n_in,
                              void* d_out, int out_size)
{
    const float* queries = (const float*)d_in[0];
    const float* keys    = (const float*)d_in[1];
    const float* values  = (const float*)d_in[2];
    const unsigned char* maskp = (const unsigned char*)d_in[3];
    const float* Wq = (const float*)d_in[4];
    const float* bq = (const float*)d_in[5];
    const float* Wk = (const float*)d_in[6];
    const float* bk = (const float*)d_in[7];
    const float* Wv = (const float*)d_in[8];
    const float* bv = (const float*)d_in[9];
    const float* Wo = (const float*)d_in[10];
    const float* bo = (const float*)d_in[11];
    float* out = (float*)d_out;

    float *qb, *kb, *vb, *ab;
    cudaGetSymbolAddress((void**)&qb, g_q);
    cudaGetSymbolAddress((void**)&kb, g_k);
    cudaGetSymbolAddress((void**)&vb, g_v);
    cudaGetSymbolAddress((void**)&ab, g_attn);

    cudaFuncSetAttribute(attn_kernel,
                         cudaFuncAttributeMaxDynamicSharedMemorySize, ATTN_SMEM);

    dim3 gg(DMODEL / BN, MTOK / BM);   // (8, 32)
    sgemm_bias<<<gg, 256>>>(queries, Wq, bq, qb, MTOK, DMODEL, DMODEL);
    sgemm_bias<<<gg, 256>>>(keys,    Wk, bk, kb, MTOK, DMODEL, DMODEL);
    sgemm_bias<<<gg, 256>>>(values,  Wv, bv, vb, MTOK, DMODEL, DMODEL);

    dim3 ga(SEQ / TS, NHEAD, BATCH);   // (32, 16, 2)
    attn_kernel<<<ga, 256, ATTN_SMEM>>>(qb, kb, vb, maskp, ab);

    sgemm_bias<<<gg, 256>>>(ab, Wo, bo, out, MTOK, DMODEL, DMODEL);
}

// round 3
// speedup vs baseline: 1.1200x; 1.1200x over previous
#include <cuda_runtime.h>
#include <cuda_bf16.h>
#include <math.h>

// Problem constants
#define BATCH 2
#define SEQ   2048
#define DMODEL 1024
#define NHEAD 16
#define HDIM  64
#define MTOK  (BATCH*SEQ)        // 4096 tokens

// ---------------------------------------------------------------------------
// Scratch (device globals; allocation-free)
// ---------------------------------------------------------------------------
__device__ float g_q[MTOK * DMODEL];
__device__ float g_k[MTOK * DMODEL];
__device__ float g_v[MTOK * DMODEL];
__device__ float g_attn[MTOK * DMODEL];

// ---------------------------------------------------------------------------
// TF32 tensor-core GEMM: C[M,N] = A[M,K] @ W[K,N] + bias
// Block tile 128x128x32, 256 threads = 8 warps (4 x 2), warp tile 32x64,
// mma.sync.m16n8k8.tf32. A staged as As[m][k] stride 36 (conflict-free
// fragment loads); B staged as Bs[k][n] stride 132 (<=2-way).
// ---------------------------------------------------------------------------
#define GBM 128
#define GBN 128
#define GBK 32
#define ASTR 36     // GBK + 4
#define BSTR 132    // GBN + 4

__device__ __forceinline__ unsigned f2tf32(float x) {
    unsigned r;
    asm("cvt.rna.tf32.f32 %0, %1;" : "=r"(r) : "f"(x));
    return r;
}

__global__ __launch_bounds__(256) void gemm_tf32(
    const float* __restrict__ A, const float* __restrict__ W,
    const float* __restrict__ bias, float* __restrict__ C,
    int M, int N, int K)
{
    __shared__ unsigned As[GBM * ASTR];   // [m][k]
    __shared__ unsigned Bs[GBK * BSTR];   // [k][n]

    const int tid = threadIdx.x;
    const int bm = blockIdx.y * GBM;
    const int bn = blockIdx.x * GBN;

    const int wid  = tid >> 5;
    const int lane = tid & 31;
    const int wm = (wid & 3) * 32;        // warp row offset in tile
    const int wn = (wid >> 2) * 64;       // warp col offset in tile
    const int gid = lane >> 2;            // 0..7
    const int tg  = lane & 3;             // 0..3

    float acc[2][8][4];
#pragma unroll
    for (int mi = 0; mi < 2; mi++)
#pragma unroll
        for (int ni = 0; ni < 8; ni++)
#pragma unroll
            for (int c = 0; c < 4; c++) acc[mi][ni][c] = 0.f;

    // staging indices
    const int a_row = tid >> 1;            // 0..127 (two threads per 32-float row)
    const int a_c4  = (tid & 1) * 4;       // 0 or 4 (float4 index)
    const int b_row = tid >> 5;            // will iterate +8 each of 4 steps? no:
    // B tile 32 rows x 128 cols = 1024 float4; 256 threads -> 4 each
    // idx = i*256 + tid ; k = idx>>5 ; c4 = idx&31

    for (int k0 = 0; k0 < K; k0 += GBK) {
        // --- stage A (128x32) ---
        {
            // idx = i*256+tid, 2 iters of 512 float4? total 128*8=1024 f4, 4 per thread
#pragma unroll
            for (int i = 0; i < 4; i++) {
                int idx = i * 256 + tid;
                int r  = idx >> 3;         // row 0..127
                int c4 = idx & 7;          // 0..7
                float4 v = *(const float4*)(A + (size_t)(bm + r) * K + k0 + c4 * 4);
                unsigned* dst = &As[r * ASTR + c4 * 4];
                dst[0] = f2tf32(v.x);
                dst[1] = f2tf32(v.y);
                dst[2] = f2tf32(v.z);
                dst[3] = f2tf32(v.w);
            }
        }
        // --- stage B (32x128) ---
        {
#pragma unroll
            for (int i = 0; i < 4; i++) {
                int idx = i * 256 + tid;
                int k  = idx >> 5;         // 0..31
                int c4 = idx & 31;         // 0..31
                float4 v = *(const float4*)(W + (size_t)(k0 + k) * N + bn + c4 * 4);
                unsigned* dst = &Bs[k * BSTR + c4 * 4];
                dst[0] = f2tf32(v.x);
                dst[1] = f2tf32(v.y);
                dst[2] = f2tf32(v.z);
                dst[3] = f2tf32(v.w);
            }
        }
        __syncthreads();

#pragma unroll
        for (int kk = 0; kk < GBK; kk += 8) {
            // A fragments: 2 x (16x8)
            unsigned af[2][4];
#pragma unroll
            for (int mi = 0; mi < 2; mi++) {
                int rb = wm + mi * 16;
                af[mi][0] = As[(rb + gid) * ASTR + kk + tg];
                af[mi][1] = As[(rb + gid + 8) * ASTR + kk + tg];
                af[mi][2] = As[(rb + gid) * ASTR + kk + tg + 4];
                af[mi][3] = As[(rb + gid + 8) * ASTR + kk + tg + 4];
            }
            // B fragments: 8 x (8x8)
            unsigned bf[8][2];
#pragma unroll
            for (int ni = 0; ni < 8; ni++) {
                int nb = wn + ni * 8 + gid;
                bf[ni][0] = Bs[(kk + tg) * BSTR + nb];
                bf[ni][1] = Bs[(kk + tg + 4) * BSTR + nb];
            }
#pragma unroll
            for (int mi = 0; mi < 2; mi++)
#pragma unroll
                for (int ni = 0; ni < 8; ni++) {
                    asm volatile(
                        "mma.sync.aligned.m16n8k8.row.col.f32.tf32.tf32.f32 "
                        "{%0,%1,%2,%3}, {%4,%5,%6,%7}, {%8,%9}, {%0,%1,%2,%3};"
                        : "+f"(acc[mi][ni][0]), "+f"(acc[mi][ni][1]),
                          "+f"(acc[mi][ni][2]), "+f"(acc[mi][ni][3])
                        : "r"(af[mi][0]), "r"(af[mi][1]),
                          "r"(af[mi][2]), "r"(af[mi][3]),
                          "r"(bf[ni][0]), "r"(bf[ni][1]));
                }
        }
        __syncthreads();
    }

    // epilogue: bias + store. c0,c1 -> (row, col..col+1); c2,c3 -> (row+8, ...)
#pragma unroll
    for (int mi = 0; mi < 2; mi++) {
        int row0 = bm + wm + mi * 16 + gid;
#pragma unroll
        for (int ni = 0; ni < 8; ni++) {
            int col = bn + wn + ni * 8 + tg * 2;
            float b0 = bias[col], b1 = bias[col + 1];
            float2 v0 = make_float2(acc[mi][ni][0] + b0, acc[mi][ni][1] + b1);
            float2 v1 = make_float2(acc[mi][ni][2] + b0, acc[mi][ni][3] + b1);
            *(float2*)(C + (size_t)row0 * N + col) = v0;
            *(float2*)(C + (size_t)(row0 + 8) * N + col) = v1;
        }
    }
}

// ---------------------------------------------------------------------------
// Flash attention: one block per (b, h, 64-query tile).  (unchanged from R0)
// ---------------------------------------------------------------------------
#define TS 64
#define TSTR 68
#define ATTN_SMEM (4 * TS * TSTR * (int)sizeof(float))

__global__ __launch_bounds__(256) void attn_kernel(
    const float* __restrict__ Q, const float* __restrict__ K,
    const float* __restrict__ V, const unsigned char* __restrict__ maskp,
    float* __restrict__ O)
{
    extern __shared__ float sm[];
    float* Qs = sm;
    float* Ks = Qs + TS * TSTR;
    float* Vs = Ks + TS * TSTR;
    float* Ps = Vs + TS * TSTR;

    const int tid = threadIdx.x;
    const int qt = blockIdx.x;
    const int h  = blockIdx.y;
    const int b  = blockIdx.z;

    const int r  = tid >> 2;
    const int qd = tid & 3;
    const int j0 = qd * 16;

    const int tok0 = b * SEQ + qt * TS;

    {
        const float* Qg = Q + (size_t)tok0 * DMODEL + h * HDIM;
#pragma unroll
        for (int i = 0; i < 4; i++) {
            int f4 = tid + i * 256;
            int rr = f4 >> 4;
            int c4 = f4 & 15;
            float4 v = *(const float4*)(Qg + (size_t)rr * DMODEL + c4 * 4);
            v.x *= 0.125f; v.y *= 0.125f; v.z *= 0.125f; v.w *= 0.125f;
            *(float4*)&Qs[rr * TSTR + c4 * 4] = v;
        }
    }

    float m = -1e30f, l = 0.f;
    float acc[16];
#pragma unroll
    for (int i = 0; i < 16; i++) acc[i] = 0.f;

    const int qglob = qt * TS + r;

    for (int kt = 0; kt <= qt; kt++) {
        __syncthreads();

        {
            const float* Kg = K + (size_t)(b * SEQ + kt * TS) * DMODEL + h * HDIM;
            const float* Vg = V + (size_t)(b * SEQ + kt * TS) * DMODEL + h * HDIM;
#pragma unroll
            for (int i = 0; i < 4; i++) {
                int f4 = tid + i * 256;
                int rr = f4 >> 4;
                int c4 = f4 & 15;
                *(float4*)&Ks[rr * TSTR + c4 * 4] =
                    *(const float4*)(Kg + (size_t)rr * DMODEL + c4 * 4);
                *(float4*)&Vs[rr * TSTR + c4 * 4] =
                    *(const float4*)(Vg + (size_t)rr * DMODEL + c4 * 4);
            }
        }
        __syncthreads();

        float s[16];
#pragma unroll
        for (int jj = 0; jj < 16; jj++) s[jj] = 0.f;
#pragma unroll
        for (int d4 = 0; d4 < 16; d4++) {
            float4 q4 = *(const float4*)&Qs[r * TSTR + d4 * 4];
#pragma unroll
            for (int jj = 0; jj < 16; jj++) {
                float4 k4 = *(const float4*)&Ks[(j0 + jj) * TSTR + d4 * 4];
                s[jj] = fmaf(q4.x, k4.x, s[jj]);
                s[jj] = fmaf(q4.y, k4.y, s[jj]);
                s[jj] = fmaf(q4.z, k4.z, s[jj]);
                s[jj] = fmaf(q4.w, k4.w, s[jj]);
            }
        }

        const int kbase = kt * TS + j0;
#pragma unroll
        for (int jj = 0; jj < 16; jj++) {
            int kglob = kbase + jj;
            if (kglob > qglob || maskp[b * SEQ + kglob]) s[jj] = -1e30f;
        }

        float tm = s[0];
#pragma unroll
        for (int jj = 1; jj < 16; jj++) tm = fmaxf(tm, s[jj]);
        tm = fmaxf(tm, __shfl_xor_sync(0xffffffffu, tm, 1));
        tm = fmaxf(tm, __shfl_xor_sync(0xffffffffu, tm, 2));
        float newm = fmaxf(m, tm);

        float ls = 0.f;
#pragma unroll
        for (int jj = 0; jj < 16; jj++) {
            float p = (s[jj] > -1e29f) ? __expf(s[jj] - newm) : 0.f;
            ls += p;
            Ps[r * TSTR + j0 + jj] = p;
        }
        ls += __shfl_xor_sync(0xffffffffu, ls, 1);
        ls += __shfl_xor_sync(0xffffffffu, ls, 2);

        float corr = (m > -1e29f) ? __expf(m - newm) : 0.f;
        l = l * corr + ls;
#pragma unroll
        for (int dd = 0; dd < 16; dd++) acc[dd] *= corr;
        m = newm;

        __syncthreads();

#pragma unroll 4
        for (int j = 0; j < TS; j++) {
            float pv = Ps[r * TSTR + j];
            const float4* vr = (const float4*)&Vs[j * TSTR + j0];
            float4 v0 = vr[0], v1 = vr[1], v2 = vr[2], v3 = vr[3];
            acc[0]  = fmaf(pv, v0.x, acc[0]);  acc[1]  = fmaf(pv, v0.y, acc[1]);
            acc[2]  = fmaf(pv, v0.z, acc[2]);  acc[3]  = fmaf(pv, v0.w, acc[3]);
            acc[4]  = fmaf(pv, v1.x, acc[4]);  acc[5]  = fmaf(pv, v1.y, acc[5]);
            acc[6]  = fmaf(pv, v1.z, acc[6]);  acc[7]  = fmaf(pv, v1.w, acc[7]);
            acc[8]  = fmaf(pv, v2.x, acc[8]);  acc[9]  = fmaf(pv, v2.y, acc[9]);
            acc[10] = fmaf(pv, v2.z, acc[10]); acc[11] = fmaf(pv, v2.w, acc[11]);
            acc[12] = fmaf(pv, v3.x, acc[12]); acc[13] = fmaf(pv, v3.y, acc[13]);
            acc[14] = fmaf(pv, v3.z, acc[14]); acc[15] = fmaf(pv, v3.w, acc[15]);
        }
    }

    const float rl = (l > 0.f) ? (1.f / l) : 0.f;
    float* Og = O + (size_t)(tok0 + r) * DMODEL + h * HDIM + j0;
#pragma unroll
    for (int t = 0; t < 4; t++) {
        float4 o;
        o.x = acc[t * 4 + 0] * rl;
        o.y = acc[t * 4 + 1] * rl;
        o.z = acc[t * 4 + 2] * rl;
        o.w = acc[t * 4 + 3] * rl;
        *(float4*)(Og + t * 4) = o;
    }
}

// ---------------------------------------------------------------------------
// Launch
// ---------------------------------------------------------------------------
extern "C" void kernel_launch(void* const* d_in, const int* in_sizes, int n_in,
                              void* d_out, int out_size)
{
    const float* queries = (const float*)d_in[0];
    const float* keys    = (const float*)d_in[1];
    const float* values  = (const float*)d_in[2];
    const unsigned char* maskp = (const unsigned char*)d_in[3];
    const float* Wq = (const float*)d_in[4];
    const float* bq = (const float*)d_in[5];
    const float* Wk = (const float*)d_in[6];
    const float* bk = (const float*)d_in[7];
    const float* Wv = (const float*)d_in[8];
    const float* bv = (const float*)d_in[9];
    const float* Wo = (const float*)d_in[10];
    const float* bo = (const float*)d_in[11];
    float* out = (float*)d_out;

    float *qb, *kb, *vb, *ab;
    cudaGetSymbolAddress((void**)&qb, g_q);
    cudaGetSymbolAddress((void**)&kb, g_k);
    cudaGetSymbolAddress((void**)&vb, g_v);
    cudaGetSymbolAddress((void**)&ab, g_attn);

    cudaFuncSetAttribute(attn_kernel,
                         cudaFuncAttributeMaxDynamicSharedMemorySize, ATTN_SMEM);

    dim3 gg(DMODEL / GBN, MTOK / GBM);   // (8, 32)
    gemm_tf32<<<gg, 256>>>(queries, Wq, bq, qb, MTOK, DMODEL, DMODEL);
    gemm_tf32<<<gg, 256>>>(keys,    Wk, bk, kb, MTOK, DMODEL, DMODEL);
    gemm_tf32<<<gg, 256>>>(values,  Wv, bv, vb, MTOK, DMODEL, DMODEL);

    dim3 ga(SEQ / TS, NHEAD, BATCH);     // (32, 16, 2)
    attn_kernel<<<ga, 256, ATTN_SMEM>>>(qb, kb, vb, maskp, ab);

    gemm_tf32<<<gg, 256>>>(ab, Wo, bo, out, MTOK, DMODEL, DMODEL);
}

// round 4
// speedup vs baseline: 8.5421x; 7.6266x over previous
#include <cuda_runtime.h>
#include <cuda_bf16.h>
#include <math.h>

// Problem constants
#define BATCH 2
#define SEQ   2048
#define DMODEL 1024
#define NHEAD 16
#define HDIM  64
#define MTOK  (BATCH*SEQ)        // 4096 tokens

// ---------------------------------------------------------------------------
// Scratch (device globals; allocation-free)
// ---------------------------------------------------------------------------
__device__ float g_q[MTOK * DMODEL];
__device__ float g_k[MTOK * DMODEL];
__device__ float g_v[MTOK * DMODEL];
__device__ float g_attn[MTOK * DMODEL];

__device__ __forceinline__ unsigned f2tf32(float x) {
    unsigned r;
    asm("cvt.rna.tf32.f32 %0, %1;" : "=r"(r) : "f"(x));
    return r;
}

#define MMA_TF32(acc, a, b0, b1)                                           \
    asm volatile(                                                          \
        "mma.sync.aligned.m16n8k8.row.col.f32.tf32.tf32.f32 "              \
        "{%0,%1,%2,%3}, {%4,%5,%6,%7}, {%8,%9}, {%0,%1,%2,%3};"            \
        : "+f"((acc)[0]), "+f"((acc)[1]), "+f"((acc)[2]), "+f"((acc)[3])   \
        : "r"((a)[0]), "r"((a)[1]), "r"((a)[2]), "r"((a)[3]),              \
          "r"(b0), "r"(b1))

// ---------------------------------------------------------------------------
// TF32 tensor-core GEMM: C[M,N] = A[M,K] @ W[K,N] + bias   (unchanged R2)
// ---------------------------------------------------------------------------
#define GBM 128
#define GBN 128
#define GBK 32
#define ASTR 36
#define BSTR 132

__global__ __launch_bounds__(256) void gemm_tf32(
    const float* __restrict__ A, const float* __restrict__ W,
    const float* __restrict__ bias, float* __restrict__ C,
    int M, int N, int K)
{
    __shared__ unsigned As[GBM * ASTR];   // [m][k]
    __shared__ unsigned Bs[GBK * BSTR];   // [k][n]

    const int tid = threadIdx.x;
    const int bm = blockIdx.y * GBM;
    const int bn = blockIdx.x * GBN;

    const int wid  = tid >> 5;
    const int lane = tid & 31;
    const int wm = (wid & 3) * 32;
    const int wn = (wid >> 2) * 64;
    const int gid = lane >> 2;
    const int tg  = lane & 3;

    float acc[2][8][4];
#pragma unroll
    for (int mi = 0; mi < 2; mi++)
#pragma unroll
        for (int ni = 0; ni < 8; ni++)
#pragma unroll
            for (int c = 0; c < 4; c++) acc[mi][ni][c] = 0.f;

    for (int k0 = 0; k0 < K; k0 += GBK) {
#pragma unroll
        for (int i = 0; i < 4; i++) {
            int idx = i * 256 + tid;
            int r  = idx >> 3;
            int c4 = idx & 7;
            float4 v = *(const float4*)(A + (size_t)(bm + r) * K + k0 + c4 * 4);
            unsigned* dst = &As[r * ASTR + c4 * 4];
            dst[0] = f2tf32(v.x); dst[1] = f2tf32(v.y);
            dst[2] = f2tf32(v.z); dst[3] = f2tf32(v.w);
        }
#pragma unroll
        for (int i = 0; i < 4; i++) {
            int idx = i * 256 + tid;
            int k  = idx >> 5;
            int c4 = idx & 31;
            float4 v = *(const float4*)(W + (size_t)(k0 + k) * N + bn + c4 * 4);
            unsigned* dst = &Bs[k * BSTR + c4 * 4];
            dst[0] = f2tf32(v.x); dst[1] = f2tf32(v.y);
            dst[2] = f2tf32(v.z); dst[3] = f2tf32(v.w);
        }
        __syncthreads();

#pragma unroll
        for (int kk = 0; kk < GBK; kk += 8) {
            unsigned af[2][4];
#pragma unroll
            for (int mi = 0; mi < 2; mi++) {
                int rb = wm + mi * 16;
                af[mi][0] = As[(rb + gid) * ASTR + kk + tg];
                af[mi][1] = As[(rb + gid + 8) * ASTR + kk + tg];
                af[mi][2] = As[(rb + gid) * ASTR + kk + tg + 4];
                af[mi][3] = As[(rb + gid + 8) * ASTR + kk + tg + 4];
            }
            unsigned bf[8][2];
#pragma unroll
            for (int ni = 0; ni < 8; ni++) {
                int nb = wn + ni * 8 + gid;
                bf[ni][0] = Bs[(kk + tg) * BSTR + nb];
                bf[ni][1] = Bs[(kk + tg + 4) * BSTR + nb];
            }
#pragma unroll
            for (int mi = 0; mi < 2; mi++)
#pragma unroll
                for (int ni = 0; ni < 8; ni++)
                    MMA_TF32(acc[mi][ni], af[mi], bf[ni][0], bf[ni][1]);
        }
        __syncthreads();
    }

#pragma unroll
    for (int mi = 0; mi < 2; mi++) {
        int row0 = bm + wm + mi * 16 + gid;
#pragma unroll
        for (int ni = 0; ni < 8; ni++) {
            int col = bn + wn + ni * 8 + tg * 2;
            float b0 = bias[col], b1 = bias[col + 1];
            float2 v0 = make_float2(acc[mi][ni][0] + b0, acc[mi][ni][1] + b1);
            float2 v1 = make_float2(acc[mi][ni][2] + b0, acc[mi][ni][3] + b1);
            *(float2*)(C + (size_t)row0 * N + col) = v0;
            *(float2*)(C + (size_t)(row0 + 8) * N + col) = v1;
        }
    }
}

// ---------------------------------------------------------------------------
// Tensor-core flash attention (tf32 mma.m16n8k8).
// Block = (b, h, 64-query tile), 128 threads = 4 warps, warp owns 16 q-rows.
// Q A-frags persistent in registers. K smem stride 68, V smem stride 72
// (both conflict-free for their fragment patterns). P stays in registers:
// C-layout -> A-layout via shfl.
// ---------------------------------------------------------------------------
#define ATS 64
#define QSTRD 68
#define KSTRD 68
#define VSTRD 72
#define ATTN_SMEM ((ATS*QSTRD + ATS*KSTRD + ATS*VSTRD + ATS) * (int)sizeof(float))

__global__ __launch_bounds__(128) void attn_mma(
    const float* __restrict__ Q, const float* __restrict__ K,
    const float* __restrict__ V, const unsigned char* __restrict__ maskp,
    float* __restrict__ O)
{
    extern __shared__ float sm[];
    unsigned* Qs = (unsigned*)sm;                    // [64][68]
    unsigned* Ks = Qs + ATS * QSTRD;                 // [64][68]
    unsigned* Vs = Ks + ATS * KSTRD;                 // [64][72]
    float*    Madd = (float*)(Vs + ATS * VSTRD);     // [64]

    const int tid  = threadIdx.x;
    const int qt = blockIdx.x, h = blockIdx.y, b = blockIdx.z;
    const int lane = tid & 31, w = tid >> 5;
    const int gid = lane >> 2, tg = lane & 3;
    const int qb = w * 16;
    const int tok0 = b * SEQ + qt * ATS;

    // ---- stage Q (scaled by 1/sqrt(64), tf32) ----
    {
        const float* Qg = Q + (size_t)tok0 * DMODEL + h * HDIM;
#pragma unroll
        for (int i = 0; i < 8; i++) {
            int idx = i * 128 + tid;
            int rr = idx >> 4, c4 = idx & 15;
            float4 v = *(const float4*)(Qg + (size_t)rr * DMODEL + c4 * 4);
            unsigned* dst = &Qs[rr * QSTRD + c4 * 4];
            dst[0] = f2tf32(v.x * 0.125f); dst[1] = f2tf32(v.y * 0.125f);
            dst[2] = f2tf32(v.z * 0.125f); dst[3] = f2tf32(v.w * 0.125f);
        }
    }
    __syncthreads();

    // ---- persistent Q A-fragments ----
    unsigned qa[8][4];
#pragma unroll
    for (int kc = 0; kc < 8; kc++) {
        qa[kc][0] = Qs[(qb + gid)     * QSTRD + kc * 8 + tg];
        qa[kc][1] = Qs[(qb + gid + 8) * QSTRD + kc * 8 + tg];
        qa[kc][2] = Qs[(qb + gid)     * QSTRD + kc * 8 + tg + 4];
        qa[kc][3] = Qs[(qb + gid + 8) * QSTRD + kc * 8 + tg + 4];
    }

    float oa[8][4];
#pragma unroll
    for (int ni = 0; ni < 8; ni++)
#pragma unroll
        for (int c = 0; c < 4; c++) oa[ni][c] = 0.f;

    float mA = -1e30f, mB = -1e30f, lA = 0.f, lB = 0.f;
    const int rowAg = qt * ATS + qb + gid;   // global (within-seq) query rows
    const int rowBg = rowAg + 8;

    for (int kt = 0; kt <= qt; kt++) {
        __syncthreads();
        // ---- stage K, V (tf32), additive mask ----
        {
            const float* Kg = K + (size_t)(b * SEQ + kt * ATS) * DMODEL + h * HDIM;
            const float* Vg = V + (size_t)(b * SEQ + kt * ATS) * DMODEL + h * HDIM;
#pragma unroll
            for (int i = 0; i < 8; i++) {
                int idx = i * 128 + tid;
                int rr = idx >> 4, c4 = idx & 15;
                float4 kv = *(const float4*)(Kg + (size_t)rr * DMODEL + c4 * 4);
                unsigned* kd = &Ks[rr * KSTRD + c4 * 4];
                kd[0] = f2tf32(kv.x); kd[1] = f2tf32(kv.y);
                kd[2] = f2tf32(kv.z); kd[3] = f2tf32(kv.w);
                float4 vv = *(const float4*)(Vg + (size_t)rr * DMODEL + c4 * 4);
                unsigned* vd = &Vs[rr * VSTRD + c4 * 4];
                vd[0] = f2tf32(vv.x); vd[1] = f2tf32(vv.y);
                vd[2] = f2tf32(vv.z); vd[3] = f2tf32(vv.w);
            }
            if (tid < ATS)
                Madd[tid] = maskp[b * SEQ + kt * ATS + tid] ? -1e30f : 0.f;
        }
        __syncthreads();

        // ---- S = Q @ K^T ----
        float sacc[8][4];
#pragma unroll
        for (int ni = 0; ni < 8; ni++)
#pragma unroll
            for (int c = 0; c < 4; c++) sacc[ni][c] = 0.f;
#pragma unroll
        for (int kc = 0; kc < 8; kc++) {
#pragma unroll
            for (int ni = 0; ni < 8; ni++) {
                unsigned b0 = Ks[(ni * 8 + gid) * KSTRD + kc * 8 + tg];
                unsigned b1 = Ks[(ni * 8 + gid) * KSTRD + kc * 8 + tg + 4];
                MMA_TF32(sacc[ni], qa[kc], b0, b1);
            }
        }

        // ---- mask + online softmax ----
        const int kbase = kt * ATS;
        float tmA = -1e30f, tmB = -1e30f;
#pragma unroll
        for (int ni = 0; ni < 8; ni++) {
            int c0 = ni * 8 + 2 * tg, c1 = c0 + 1;
            float m0 = Madd[c0], m1 = Madd[c1];
            sacc[ni][0] += m0; sacc[ni][1] += m1;
            sacc[ni][2] += m0; sacc[ni][3] += m1;
            if (kbase + c0 > rowAg) sacc[ni][0] = -1e30f;
            if (kbase + c1 > rowAg) sacc[ni][1] = -1e30f;
            if (kbase + c0 > rowBg) sacc[ni][2] = -1e30f;
            if (kbase + c1 > rowBg) sacc[ni][3] = -1e30f;
            tmA = fmaxf(tmA, fmaxf(sacc[ni][0], sacc[ni][1]));
            tmB = fmaxf(tmB, fmaxf(sacc[ni][2], sacc[ni][3]));
        }
        tmA = fmaxf(tmA, __shfl_xor_sync(0xffffffffu, tmA, 1));
        tmA = fmaxf(tmA, __shfl_xor_sync(0xffffffffu, tmA, 2));
        tmB = fmaxf(tmB, __shfl_xor_sync(0xffffffffu, tmB, 1));
        tmB = fmaxf(tmB, __shfl_xor_sync(0xffffffffu, tmB, 2));

        float nmA = fmaxf(mA, tmA), nmB = fmaxf(mB, tmB);
        float corrA = (mA > -1e29f) ? __expf(mA - nmA) : 0.f;
        float corrB = (mB > -1e29f) ? __expf(mB - nmB) : 0.f;

        unsigned pu[8][4];
        float saA = 0.f, saB = 0.f;
#pragma unroll
        for (int ni = 0; ni < 8; ni++) {
            float p0 = (sacc[ni][0] > -1e29f) ? __expf(sacc[ni][0] - nmA) : 0.f;
            float p1 = (sacc[ni][1] > -1e29f) ? __expf(sacc[ni][1] - nmA) : 0.f;
            float p2 = (sacc[ni][2] > -1e29f) ? __expf(sacc[ni][2] - nmB) : 0.f;
            float p3 = (sacc[ni][3] > -1e29f) ? __expf(sacc[ni][3] - nmB) : 0.f;
            saA += p0 + p1; saB += p2 + p3;
            pu[ni][0] = f2tf32(p0); pu[ni][1] = f2tf32(p1);
            pu[ni][2] = f2tf32(p2); pu[ni][3] = f2tf32(p3);
        }
        saA += __shfl_xor_sync(0xffffffffu, saA, 1);
        saA += __shfl_xor_sync(0xffffffffu, saA, 2);
        saB += __shfl_xor_sync(0xffffffffu, saB, 1);
        saB += __shfl_xor_sync(0xffffffffu, saB, 2);

        lA = lA * corrA + saA;
        lB = lB * corrB + saB;
        mA = nmA; mB = nmB;
#pragma unroll
        for (int ni = 0; ni < 8; ni++) {
            oa[ni][0] *= corrA; oa[ni][1] *= corrA;
            oa[ni][2] *= corrB; oa[ni][3] *= corrB;
        }

        // ---- O += P @ V  (P C-layout -> A-layout via shfl) ----
        const int srcbase = lane & ~3;
#pragma unroll
        for (int kc = 0; kc < 8; kc++) {
            int s1 = srcbase + (tg >> 1);
            int s2 = s1 + 2;
            unsigned v00 = __shfl_sync(0xffffffffu, pu[kc][0], s1);
            unsigned v01 = __shfl_sync(0xffffffffu, pu[kc][1], s1);
            unsigned v10 = __shfl_sync(0xffffffffu, pu[kc][2], s1);
            unsigned v11 = __shfl_sync(0xffffffffu, pu[kc][3], s1);
            unsigned w00 = __shfl_sync(0xffffffffu, pu[kc][0], s2);
            unsigned w01 = __shfl_sync(0xffffffffu, pu[kc][1], s2);
            unsigned w10 = __shfl_sync(0xffffffffu, pu[kc][2], s2);
            unsigned w11 = __shfl_sync(0xffffffffu, pu[kc][3], s2);
            unsigned pa[4];
            pa[0] = (tg & 1) ? v01 : v00;
            pa[1] = (tg & 1) ? v11 : v10;
            pa[2] = (tg & 1) ? w01 : w00;
            pa[3] = (tg & 1) ? w11 : w10;
#pragma unroll
            for (int ni = 0; ni < 8; ni++) {
                unsigned b0 = Vs[(kc * 8 + tg)     * VSTRD + ni * 8 + gid];
                unsigned b1 = Vs[(kc * 8 + tg + 4) * VSTRD + ni * 8 + gid];
                MMA_TF32(oa[ni], pa, b0, b1);
            }
        }
    }

    // ---- epilogue ----
    const float rlA = (lA > 0.f) ? (1.f / lA) : 0.f;
    const float rlB = (lB > 0.f) ? (1.f / lB) : 0.f;
    float* Og = O + (size_t)(tok0 + qb + gid) * DMODEL + h * HDIM;
#pragma unroll
    for (int ni = 0; ni < 8; ni++) {
        int col = ni * 8 + 2 * tg;
        float2 vA = make_float2(oa[ni][0] * rlA, oa[ni][1] * rlA);
        float2 vB = make_float2(oa[ni][2] * rlB, oa[ni][3] * rlB);
        *(float2*)(Og + col) = vA;
        *(float2*)(Og + (size_t)8 * DMODEL + col) = vB;
    }
}

// ---------------------------------------------------------------------------
// Launch
// ---------------------------------------------------------------------------
extern "C" void kernel_launch(void* const* d_in, const int* in_sizes, int n_in,
                              void* d_out, int out_size)
{
    const float* queries = (const float*)d_in[0];
    const float* keys    = (const float*)d_in[1];
    const float* values  = (const float*)d_in[2];
    const unsigned char* maskp = (const unsigned char*)d_in[3];
    const float* Wq = (const float*)d_in[4];
    const float* bq = (const float*)d_in[5];
    const float* Wk = (const float*)d_in[6];
    const float* bk = (const float*)d_in[7];
    const float* Wv = (const float*)d_in[8];
    const float* bv = (const float*)d_in[9];
    const float* Wo = (const float*)d_in[10];
    const float* bo = (const float*)d_in[11];
    float* out = (float*)d_out;

    float *qb, *kb, *vb, *ab;
    cudaGetSymbolAddress((void**)&qb, g_q);
    cudaGetSymbolAddress((void**)&kb, g_k);
    cudaGetSymbolAddress((void**)&vb, g_v);
    cudaGetSymbolAddress((void**)&ab, g_attn);

    cudaFuncSetAttribute(attn_mma,
                         cudaFuncAttributeMaxDynamicSharedMemorySize, ATTN_SMEM);

    dim3 gg(DMODEL / GBN, MTOK / GBM);   // (8, 32)
    gemm_tf32<<<gg, 256>>>(queries, Wq, bq, qb, MTOK, DMODEL, DMODEL);
    gemm_tf32<<<gg, 256>>>(keys,    Wk, bk, kb, MTOK, DMODEL, DMODEL);
    gemm_tf32<<<gg, 256>>>(values,  Wv, bv, vb, MTOK, DMODEL, DMODEL);

    dim3 ga(SEQ / ATS, NHEAD, BATCH);    // (32, 16, 2)
    attn_mma<<<ga, 128, ATTN_SMEM>>>(qb, kb, vb, maskp, ab);

    gemm_tf32<<<gg, 256>>>(ab, Wo, bo, out, MTOK, DMODEL, DMODEL);
}